// round 15
// baseline (speedup 1.0000x reference)
#include <cuda_runtime.h>
#include <cuda_bf16.h>
#include <cstdint>

#define BATCH 16
#define HALF  8
#define CHAN  64
#define NPTS  65536
#define RES   (32*32*32)   // 32768
#define G     128          // reduction blocks per batch

// ---------------- scratch (device globals; no allocations allowed) ----------
__device__ float g_psum[BATCH * G * 3];            // per-block partial sums
__device__ float g_pmax[BATCH * G];                // per-block partial max-norm
__device__ int   g_voxidx[BATCH * NPTS];           // voxel index per point
__device__ int   g_counts[BATCH * RES];            // points per voxel
__device__ float g_accum[(size_t)HALF * RES * CHAN]; // [8, RES, C] sums (67MB)
// g_accum: 8*32768*64 = 16,777,216 floats = 4,194,304 float4

// ---------------- kernel 1: partial coord sums + zero counts -----------------
__global__ void mean_kernel(const float* __restrict__ coords) {
    int b  = blockIdx.y;
    int bx = blockIdx.x;
    // fold counts zeroing in (2MB of int4 stores across the grid)
    int flat = (b * G + bx) * 256 + threadIdx.x;   // 0..524287
    if (flat < BATCH * RES / 4)
        reinterpret_cast<int4*>(g_counts)[flat] = make_int4(0, 0, 0, 0);

    const float* cb = coords + (size_t)b * 3 * NPTS;
    float sx = 0.f, sy = 0.f, sz = 0.f;
    for (int n = bx * 256 + threadIdx.x; n < NPTS; n += G * 256) {
        sx += cb[n];
        sy += cb[NPTS + n];
        sz += cb[2 * NPTS + n];
    }
    for (int o = 16; o > 0; o >>= 1) {
        sx += __shfl_down_sync(0xffffffffu, sx, o);
        sy += __shfl_down_sync(0xffffffffu, sy, o);
        sz += __shfl_down_sync(0xffffffffu, sz, o);
    }
    __shared__ float shx[8], shy[8], shz[8];
    int warp = threadIdx.x >> 5, lane = threadIdx.x & 31;
    if (lane == 0) { shx[warp] = sx; shy[warp] = sy; shz[warp] = sz; }
    __syncthreads();
    if (threadIdx.x == 0) {
        float tx = 0.f, ty = 0.f, tz = 0.f;
        #pragma unroll
        for (int w = 0; w < 8; w++) { tx += shx[w]; ty += shy[w]; tz += shz[w]; }
        g_psum[(b * G + bx) * 3 + 0] = tx;
        g_psum[(b * G + bx) * 3 + 1] = ty;
        g_psum[(b * G + bx) * 3 + 2] = tz;
    }
}

// block-level reduce of G partials (redundant per block; L2-hot, cheap)
__device__ __forceinline__ void reduce_mean(int b, float& mx, float& my, float& mz) {
    __shared__ float3 sm[G];
    if (threadIdx.x < G) {
        sm[threadIdx.x] = make_float3(g_psum[(b * G + threadIdx.x) * 3 + 0],
                                      g_psum[(b * G + threadIdx.x) * 3 + 1],
                                      g_psum[(b * G + threadIdx.x) * 3 + 2]);
    }
    __syncthreads();
    #pragma unroll
    for (int s = G / 2; s > 0; s >>= 1) {
        if (threadIdx.x < s) {
            sm[threadIdx.x].x += sm[threadIdx.x + s].x;
            sm[threadIdx.x].y += sm[threadIdx.x + s].y;
            sm[threadIdx.x].z += sm[threadIdx.x + s].z;
        }
        __syncthreads();
    }
    const float inv_n = 1.0f / (float)NPTS;
    mx = sm[0].x * inv_n; my = sm[0].y * inv_n; mz = sm[0].z * inv_n;
    __syncthreads();
}

// ---------------- kernel 2: partial max squared norm -------------------------
__global__ void maxnorm_kernel(const float* __restrict__ coords) {
    int b  = blockIdx.y;
    int bx = blockIdx.x;
    float mx, my, mz;
    reduce_mean(b, mx, my, mz);

    const float* cb = coords + (size_t)b * 3 * NPTS;
    float best = 0.f;
    for (int n = bx * 256 + threadIdx.x; n < NPTS; n += G * 256) {
        float dx = cb[n] - mx;
        float dy = cb[NPTS + n] - my;
        float dz = cb[2 * NPTS + n] - mz;
        best = fmaxf(best, dx * dx + dy * dy + dz * dz);
    }
    for (int o = 16; o > 0; o >>= 1)
        best = fmaxf(best, __shfl_down_sync(0xffffffffu, best, o));
    __shared__ float sh[8];
    int warp = threadIdx.x >> 5, lane = threadIdx.x & 31;
    if (lane == 0) sh[warp] = best;
    __syncthreads();
    if (threadIdx.x == 0) {
        float t = 0.f;
        #pragma unroll
        for (int w = 0; w < 8; w++) t = fmaxf(t, sh[w]);
        g_pmax[b * G + bx] = t;
    }
}

// ---------------- kernel 3: normalize + voxidx + count + zero accum ----------
__global__ void point_kernel(const float* __restrict__ coords,
                             float* __restrict__ norm_out) {
    int b  = blockIdx.y;
    int bx = blockIdx.x;
    float mx, my, mz;
    reduce_mean(b, mx, my, mz);
    // reduce max partials
    __shared__ float smx[G];
    if (threadIdx.x < G) smx[threadIdx.x] = g_pmax[b * G + threadIdx.x];
    __syncthreads();
    #pragma unroll
    for (int s = G / 2; s > 0; s >>= 1) {
        if (threadIdx.x < s) smx[threadIdx.x] = fmaxf(smx[threadIdx.x], smx[threadIdx.x + s]);
        __syncthreads();
    }
    float inv_d = 1.0f / (sqrtf(smx[0]) * 2.0f);

    const float* cb = coords + (size_t)b * 3 * NPTS;
    float* nb = norm_out + (size_t)b * 3 * NPTS;
    for (int n = bx * 256 + threadIdx.x; n < NPTS; n += G * 256) {
        float sx = ((cb[n]            - mx) * inv_d + 0.5f) * 32.0f;
        float sy = ((cb[NPTS + n]     - my) * inv_d + 0.5f) * 32.0f;
        float sz = ((cb[2 * NPTS + n] - mz) * inv_d + 0.5f) * 32.0f;
        sx = fminf(fmaxf(sx, 0.0f), 31.0f);
        sy = fminf(fmaxf(sy, 0.0f), 31.0f);
        sz = fminf(fmaxf(sz, 0.0f), 31.0f);
        nb[n]            = sx;
        nb[NPTS + n]     = sy;
        nb[2 * NPTS + n] = sz;
        int vx = (int)rintf(sx);   // round-half-even, matches jnp.round
        int vy = (int)rintf(sy);
        int vz = (int)rintf(sz);
        int idx = (vx << 10) + (vy << 5) + vz;
        g_voxidx[(b << 16) + n] = idx;
        atomicAdd(&g_counts[b * RES + idx], 1);
    }

    // fold accum zeroing in: 524288 threads x 8 float4 = 4,194,304 float4 = 67MB
    {
        int flat = (b * G + bx) * 256 + threadIdx.x;   // 0..524287
        float4 z = make_float4(0.f, 0.f, 0.f, 0.f);
        float4* p = reinterpret_cast<float4*>(g_accum);
        #pragma unroll
        for (int k = 0; k < 8; k++)
            p[flat + k * 524288] = z;
    }
}

// ---------------- kernel 4: scatter half with v4 vector atomics --------------
// thread = (bl, cg, n); warp lanes share (bl,cg), consecutive n.
__global__ void scatter_kernel(const float* __restrict__ features, int b0) {
    int tid = blockIdx.x * blockDim.x + threadIdx.x;  // 8,388,608 threads
    int n  = tid & (NPTS - 1);
    int g  = tid >> 16;            // bl*16 + cg
    int cg = g & 15;
    int bl = g >> 4;               // 0..7
    int b  = b0 + bl;

    const float* f = features + ((size_t)(b * CHAN + cg * 4)) * NPTS + n;
    float f0 = f[0];
    float f1 = f[NPTS];
    float f2 = f[2 * NPTS];
    float f3 = f[3 * NPTS];

    int v = g_voxidx[(b << 16) + n];
    float* dst = g_accum + (((size_t)(bl * RES + v)) << 6) + (cg << 2);
    asm volatile("red.global.add.v4.f32 [%0], {%1, %2, %3, %4};"
                 :: "l"(dst), "f"(f0), "f"(f1), "f"(f2), "f"(f3)
                 : "memory");
}

// ---------------- kernel 5: transpose half -> out, /cnt, optional rezero -----
__global__ void transpose_kernel(float* __restrict__ out, int b0, int rezero) {
    __shared__ float tile[32][65];
    __shared__ float inv[32];
    int chunk = blockIdx.x;            // 0 .. HALF*1024-1
    int bl = chunk >> 10;
    int b  = b0 + bl;
    int v0 = (chunk & 1023) << 5;      // 32-voxel group

    float4* src = reinterpret_cast<float4*>(
        g_accum + (((size_t)(bl * RES + v0)) << 6));
    const float4 z4 = make_float4(0.f, 0.f, 0.f, 0.f);
    #pragma unroll
    for (int k = 0; k < 2; k++) {
        int idx = threadIdx.x + (k << 8);   // 0..511 (32 vox x 16 float4)
        int vl = idx >> 4;
        int c4 = idx & 15;
        float4 val = src[vl * 16 + c4];
        if (rezero) src[vl * 16 + c4] = z4; // ready accum for next scatter
        int c = c4 << 2;
        tile[vl][c + 0] = val.x;
        tile[vl][c + 1] = val.y;
        tile[vl][c + 2] = val.z;
        tile[vl][c + 3] = val.w;
    }
    if (threadIdx.x < 32) {
        int c = g_counts[b * RES + v0 + threadIdx.x];
        inv[threadIdx.x] = 1.0f / (float)max(c, 1);
    }
    __syncthreads();

    int lane = threadIdx.x & 31;
    int wrp  = threadIdx.x >> 5;
    #pragma unroll
    for (int k = 0; k < 8; k++) {
        int c = wrp + (k << 3);            // 0..63
        out[((size_t)(b * CHAN + c)) * RES + v0 + lane] = tile[lane][c] * inv[lane];
    }
}

// ---------------- launcher ---------------------------------------------------
extern "C" void kernel_launch(void* const* d_in, const int* in_sizes, int n_in,
                              void* d_out, int out_size) {
    const float* features = (const float*)d_in[0];  // [B, C, N]
    const float* coords   = (const float*)d_in[1];  // [B, 3, N]
    float* out = (float*)d_out;                     // [B,C,32,32,32] ++ [B,3,N]
    float* norm_out = out + (size_t)BATCH * CHAN * RES;

    dim3 grid_r(G, BATCH);
    mean_kernel<<<grid_r, 256>>>(coords);           // + zero counts
    maxnorm_kernel<<<grid_r, 256>>>(coords);
    point_kernel<<<grid_r, 256>>>(coords, norm_out); // + zero accum

    scatter_kernel<<<32768, 256>>>(features, 0);
    transpose_kernel<<<HALF * 1024, 256>>>(out, 0, 1);   // rezero for half 2

    scatter_kernel<<<32768, 256>>>(features, HALF);
    transpose_kernel<<<HALF * 1024, 256>>>(out, HALF, 0); // point rezeros next replay
}

// round 17
// speedup vs baseline: 1.5039x; 1.5039x over previous
#include <cuda_runtime.h>
#include <cuda_bf16.h>
#include <cstdint>

#define BATCH 16
#define HALF  8
#define CHAN  64
#define NPTS  65536
#define RES   (32*32*32)   // 32768
#define G     128          // reduction blocks per batch

// ---------------- scratch (device globals; no allocations allowed) ----------
__device__ float g_psum[BATCH * G * 3];            // per-block partial sums
__device__ float g_pmax[BATCH * G];                // per-block partial max-norm
__device__ int   g_voxidx[BATCH * NPTS];           // voxel index per point
__device__ int   g_counts[BATCH * RES];            // points per voxel
__device__ float g_accum[(size_t)HALF * RES * CHAN]; // [8, RES, C] sums (67MB)

// ---------------- kernel 1: partial coord sums + zero counts -----------------
__global__ void mean_kernel(const float* __restrict__ coords) {
    int b  = blockIdx.y;
    int bx = blockIdx.x;                           // G=128 blocks
    // fold counts zeroing in: 16*128*256 = 524288 threads >= 131072 int4
    int flat = (b * G + bx) * 256 + threadIdx.x;
    if (flat < BATCH * RES / 4)
        reinterpret_cast<int4*>(g_counts)[flat] = make_int4(0, 0, 0, 0);

    const float* cb = coords + (size_t)b * 3 * NPTS;
    float sx = 0.f, sy = 0.f, sz = 0.f;
    for (int n = bx * 256 + threadIdx.x; n < NPTS; n += G * 256) {
        sx += cb[n];
        sy += cb[NPTS + n];
        sz += cb[2 * NPTS + n];
    }
    for (int o = 16; o > 0; o >>= 1) {
        sx += __shfl_down_sync(0xffffffffu, sx, o);
        sy += __shfl_down_sync(0xffffffffu, sy, o);
        sz += __shfl_down_sync(0xffffffffu, sz, o);
    }
    __shared__ float shx[8], shy[8], shz[8];
    int warp = threadIdx.x >> 5, lane = threadIdx.x & 31;
    if (lane == 0) { shx[warp] = sx; shy[warp] = sy; shz[warp] = sz; }
    __syncthreads();
    if (threadIdx.x == 0) {
        float tx = 0.f, ty = 0.f, tz = 0.f;
        #pragma unroll
        for (int w = 0; w < 8; w++) { tx += shx[w]; ty += shy[w]; tz += shz[w]; }
        g_psum[(b * G + bx) * 3 + 0] = tx;
        g_psum[(b * G + bx) * 3 + 1] = ty;
        g_psum[(b * G + bx) * 3 + 2] = tz;
    }
}

// block-level reduce of G partials (redundant per block; L2-hot, cheap)
__device__ __forceinline__ void reduce_mean(int b, float& mx, float& my, float& mz) {
    __shared__ float3 sm[G];
    if (threadIdx.x < G) {
        sm[threadIdx.x] = make_float3(g_psum[(b * G + threadIdx.x) * 3 + 0],
                                      g_psum[(b * G + threadIdx.x) * 3 + 1],
                                      g_psum[(b * G + threadIdx.x) * 3 + 2]);
    }
    __syncthreads();
    #pragma unroll
    for (int s = G / 2; s > 0; s >>= 1) {
        if (threadIdx.x < s) {
            sm[threadIdx.x].x += sm[threadIdx.x + s].x;
            sm[threadIdx.x].y += sm[threadIdx.x + s].y;
            sm[threadIdx.x].z += sm[threadIdx.x + s].z;
        }
        __syncthreads();
    }
    const float inv_n = 1.0f / (float)NPTS;
    mx = sm[0].x * inv_n; my = sm[0].y * inv_n; mz = sm[0].z * inv_n;
    __syncthreads();
}

// ---------------- kernel 2: partial max squared norm -------------------------
__global__ void maxnorm_kernel(const float* __restrict__ coords) {
    int b  = blockIdx.y;
    int bx = blockIdx.x;
    float mx, my, mz;
    reduce_mean(b, mx, my, mz);

    const float* cb = coords + (size_t)b * 3 * NPTS;
    float best = 0.f;
    for (int n = bx * 256 + threadIdx.x; n < NPTS; n += G * 256) {
        float dx = cb[n] - mx;
        float dy = cb[NPTS + n] - my;
        float dz = cb[2 * NPTS + n] - mz;
        best = fmaxf(best, dx * dx + dy * dy + dz * dz);
    }
    for (int o = 16; o > 0; o >>= 1)
        best = fmaxf(best, __shfl_down_sync(0xffffffffu, best, o));
    __shared__ float sh[8];
    int warp = threadIdx.x >> 5, lane = threadIdx.x & 31;
    if (lane == 0) sh[warp] = best;
    __syncthreads();
    if (threadIdx.x == 0) {
        float t = 0.f;
        #pragma unroll
        for (int w = 0; w < 8; w++) t = fmaxf(t, sh[w]);
        g_pmax[b * G + bx] = t;
    }
}

// ---------------- kernel 3: normalize + voxidx + counts ----------------------
__global__ void point_kernel(const float* __restrict__ coords,
                             float* __restrict__ norm_out) {
    int b  = blockIdx.y;
    int bx = blockIdx.x;
    float mx, my, mz;
    reduce_mean(b, mx, my, mz);
    __shared__ float smx[G];
    if (threadIdx.x < G) smx[threadIdx.x] = g_pmax[b * G + threadIdx.x];
    __syncthreads();
    #pragma unroll
    for (int s = G / 2; s > 0; s >>= 1) {
        if (threadIdx.x < s) smx[threadIdx.x] = fmaxf(smx[threadIdx.x], smx[threadIdx.x + s]);
        __syncthreads();
    }
    float inv_d = 1.0f / (sqrtf(smx[0]) * 2.0f);

    const float* cb = coords + (size_t)b * 3 * NPTS;
    float* nb = norm_out + (size_t)b * 3 * NPTS;
    for (int n = bx * 256 + threadIdx.x; n < NPTS; n += G * 256) {
        float sx = ((cb[n]            - mx) * inv_d + 0.5f) * 32.0f;
        float sy = ((cb[NPTS + n]     - my) * inv_d + 0.5f) * 32.0f;
        float sz = ((cb[2 * NPTS + n] - mz) * inv_d + 0.5f) * 32.0f;
        sx = fminf(fmaxf(sx, 0.0f), 31.0f);
        sy = fminf(fmaxf(sy, 0.0f), 31.0f);
        sz = fminf(fmaxf(sz, 0.0f), 31.0f);
        nb[n]            = sx;
        nb[NPTS + n]     = sy;
        nb[2 * NPTS + n] = sz;
        int vx = (int)rintf(sx);   // round-half-even, matches jnp.round
        int vy = (int)rintf(sy);
        int vz = (int)rintf(sz);
        int idx = (vx << 10) + (vy << 5) + vz;
        g_voxidx[(b << 16) + n] = idx;
        atomicAdd(&g_counts[b * RES + idx], 1);
    }
}

// ---------------- kernel 4: dense zero of half accum (L2 install) ------------
__global__ void zero_accum_kernel() {
    int i = blockIdx.x * blockDim.x + threadIdx.x;   // 2,097,152 threads x 2
    float4 z = make_float4(0.f, 0.f, 0.f, 0.f);
    reinterpret_cast<float4*>(g_accum)[i]             = z;
    reinterpret_cast<float4*>(g_accum)[i + 2097152]   = z;
}

// ---------------- kernel 5: scatter half with v4 vector atomics --------------
// thread = (bl, cg, n); warp lanes share (bl,cg), consecutive n.
__global__ void scatter_kernel(const float* __restrict__ features, int b0) {
    int tid = blockIdx.x * blockDim.x + threadIdx.x;  // 8,388,608 threads
    int n  = tid & (NPTS - 1);
    int g  = tid >> 16;            // bl*16 + cg
    int cg = g & 15;
    int bl = g >> 4;               // 0..7
    int b  = b0 + bl;

    const float* f = features + ((size_t)(b * CHAN + cg * 4)) * NPTS + n;
    float f0 = f[0];
    float f1 = f[NPTS];
    float f2 = f[2 * NPTS];
    float f3 = f[3 * NPTS];

    int v = g_voxidx[(b << 16) + n];
    float* dst = g_accum + (((size_t)(bl * RES + v)) << 6) + (cg << 2);
    asm volatile("red.global.add.v4.f32 [%0], {%1, %2, %3, %4};"
                 :: "l"(dst), "f"(f0), "f"(f1), "f"(f2), "f"(f3)
                 : "memory");
}

// ---------------- kernel 6: transpose half [8,RES,C] -> out[B,C,RES], /cnt ---
__global__ void transpose_kernel(float* __restrict__ out, int b0) {
    __shared__ float tile[32][65];
    __shared__ float inv[32];
    int chunk = blockIdx.x;            // 0 .. HALF*1024-1
    int bl = chunk >> 10;
    int b  = b0 + bl;
    int v0 = (chunk & 1023) << 5;      // 32-voxel group

    const float4* src = reinterpret_cast<const float4*>(
        g_accum + (((size_t)(bl * RES + v0)) << 6));
    #pragma unroll
    for (int k = 0; k < 2; k++) {
        int idx = threadIdx.x + (k << 8);   // 0..511 (32 vox x 16 float4)
        int vl = idx >> 4;
        int c4 = idx & 15;
        float4 val = src[vl * 16 + c4];
        int c = c4 << 2;
        tile[vl][c + 0] = val.x;
        tile[vl][c + 1] = val.y;
        tile[vl][c + 2] = val.z;
        tile[vl][c + 3] = val.w;
    }
    if (threadIdx.x < 32) {
        int c = g_counts[b * RES + v0 + threadIdx.x];
        inv[threadIdx.x] = 1.0f / (float)max(c, 1);
    }
    __syncthreads();

    int lane = threadIdx.x & 31;
    int wrp  = threadIdx.x >> 5;
    #pragma unroll
    for (int k = 0; k < 8; k++) {
        int c = wrp + (k << 3);            // 0..63
        out[((size_t)(b * CHAN + c)) * RES + v0 + lane] = tile[lane][c] * inv[lane];
    }
}

// ---------------- launcher ---------------------------------------------------
extern "C" void kernel_launch(void* const* d_in, const int* in_sizes, int n_in,
                              void* d_out, int out_size) {
    const float* features = (const float*)d_in[0];  // [B, C, N]
    const float* coords   = (const float*)d_in[1];  // [B, 3, N]
    float* out = (float*)d_out;                     // [B,C,32,32,32] ++ [B,3,N]
    float* norm_out = out + (size_t)BATCH * CHAN * RES;

    dim3 grid_r(G, BATCH);
    mean_kernel<<<grid_r, 256>>>(coords);            // + zero counts
    maxnorm_kernel<<<grid_r, 256>>>(coords);
    point_kernel<<<grid_r, 256>>>(coords, norm_out);

    // two halves: 67MB accum, dense zero installs L2 right before scatter
    zero_accum_kernel<<<8192, 256>>>();
    scatter_kernel<<<32768, 256>>>(features, 0);
    transpose_kernel<<<HALF * 1024, 256>>>(out, 0);

    zero_accum_kernel<<<8192, 256>>>();
    scatter_kernel<<<32768, 256>>>(features, HALF);
    transpose_kernel<<<HALF * 1024, 256>>>(out, HALF);
}